// round 11
// baseline (speedup 1.0000x reference)
#include <cuda_runtime.h>

#define NCHUNKS 32
#define ROWS    64
#define THREADS 1024
#define XPAD    257               // smem row stride in floats (conflict-free)
#define MAX_ATOMS   16384
#define MAX_CLAUSES 4096

// Padded per-atom metadata stream. Every clause is padded to a multiple of 4
// atoms, every chunk to a multiple of 8. Flush can only occur on atom3 of a
// 4-atom group (bit31 of .z set there; .w = gate*leaf of the clause).
// Identity pad atoms: {0, -1000, 0, 0} -> e ~ 1e-301 -> fmaxf clamp -> p unchanged.
// arg = A'*x[fid] + B' ; e = exp2(arg) ; clause = 1/prod(1+e)
__device__ float4 g_meta[MAX_ATOMS];
__device__ int    g_chunk_start[NCHUNKS + 1]; // 8-aligned padded ranges
__device__ float  g_empty[NCHUNKS];           // sum g over EMPTY clauses per chunk

__device__ __forceinline__ float ex2a(float a) {
    float r; asm("ex2.approx.f32 %0, %1;" : "=f"(r) : "f"(a)); return r;
}
__device__ __forceinline__ float rcpa(float a) {
    float r; asm("rcp.approx.f32 %0, %1;" : "=f"(r) : "f"(a)); return r;
}

// Single-block setup: smem-staged cids, per-clause searches in smem,
// per-chunk serial mini-scan (32 chunks), atom-parallel meta build.
__global__ void cln_setup(const float* __restrict__ w,
                          const float* __restrict__ eta,
                          const float* __restrict__ leaf,
                          const float* __restrict__ gate,
                          const int* __restrict__ fid,
                          const int* __restrict__ csgn,
                          const int* __restrict__ cids,
                          int n_atoms, int n_clauses, int cpc) {
    extern __shared__ int sm[];
    int*   s_cids = sm;                      // n_atoms
    int*   s_src  = sm + n_atoms;            // n_clauses
    int*   s_plen = s_src + n_clauses;       // n_clauses
    int*   s_dst  = s_plen + n_clauses;      // n_clauses (abs padded offset)
    float* s_g    = (float*)(s_dst + n_clauses);
    __shared__ int s_cbase[NCHUNKS + 1];

    const int tid = threadIdx.x;
    const float L2E = 1.4426950408889634f;

    for (int i = tid; i < n_atoms; i += blockDim.x) s_cids[i] = cids[i];
    __syncthreads();

    int len = 0, lo = 0, plen = 0;
    float g = 0.f;
    if (tid < n_clauses) {
        int hi = n_atoms;
        while (lo < hi) { int m = (lo + hi) >> 1; if (s_cids[m] < tid) lo = m + 1; else hi = m; }
        int lo2 = lo, hi2 = n_atoms;
        while (lo2 < hi2) { int m = (lo2 + hi2) >> 1; if (s_cids[m] < tid + 1) lo2 = m + 1; else hi2 = m; }
        len  = lo2 - lo;
        plen = (len + 3) & ~3;
        g = gate[tid] * leaf[tid];
        s_src[tid]  = lo;
        s_plen[tid] = plen;
        s_g[tid]    = g;
        if (len == 0) atomicAdd(&g_empty[tid / cpc], g);
    }
    __syncthreads();

    // per-chunk relative offsets + chunk lengths
    int clen = 0;
    if (tid < NCHUNKS) {
        int rel = 0;
        for (int j = 0; j < cpc; ++j) {
            int c = tid * cpc + j;
            s_dst[c] = rel;                  // relative for now
            rel += s_plen[c];
        }
        clen = rel;                          // unpadded chunk length (mult of 4)
        s_cbase[tid] = (rel + 7) & ~7;       // padded length, scanned below
    }
    __syncthreads();
    if (tid == 0) {
        int acc = 0;
        for (int k = 0; k < NCHUNKS; ++k) {
            int l = s_cbase[k];
            s_cbase[k] = acc;
            g_chunk_start[k] = acc;
            acc += l;
        }
        s_cbase[NCHUNKS] = acc;
        g_chunk_start[NCHUNKS] = acc;
    }
    __syncthreads();
    if (tid < n_clauses) s_dst[tid] += s_cbase[tid / cpc];
    __syncthreads();

    // atom-parallel meta build (coalesced input loads, computed scatter)
    for (int i = tid; i < n_atoms; i += blockDim.x) {
        int c = s_cids[i];
        int j = i - s_src[c];
        float sB = (csgn[i] == 0) ? -100.0f : 100.0f;   // sign * B_CONST
        float A2 = -sB * w[i] * L2E;
        float B2 = -sB * (0.01f - eta[i]) * L2E;        // EPS = 0.01
        int fz = fid[i];
        float gg = 0.f;
        if (j == s_plen[c] - 1) { fz |= 0x80000000; gg = s_g[c]; }
        g_meta[s_dst[c] + j] = make_float4(A2, B2, __int_as_float(fz), gg);
    }
    // clause pads (identity; flush flag on final padded slot)
    if (tid < n_clauses && len > 0) {
        int dst = s_dst[tid];
        for (int j = len; j < plen; ++j) {
            int fz = 0; float gg = 0.f;
            if (j == plen - 1) { fz = 0x80000000; gg = g; }
            g_meta[dst + j] = make_float4(0.f, -1000.f, __int_as_float(fz), gg);
        }
    }
    // chunk pads to multiple of 8 (identity, NON-flush group; p discarded)
    if (tid < NCHUNKS) {
        int base = s_cbase[tid];
        int pend = s_cbase[tid + 1] - base;  // padded chunk length
        for (int a = clen; a < pend; ++a)
            g_meta[base + a] = make_float4(0.f, -1000.f, 0.f, 0.f);
    }
}

__global__ __launch_bounds__(THREADS, 1)
void cln_main(const float* __restrict__ x, float* __restrict__ y, int nfeat) {
    extern __shared__ float xs[];            // ROWS * XPAD floats
    __shared__ float ys[ROWS];

    const int rowBase = blockIdx.x * ROWS;

    // Stage 64 rows of x into shared (coalesced float4 loads)
    const int n4f = nfeat >> 2;
    for (int i = threadIdx.x; i < ROWS * n4f; i += THREADS) {
        int row = i / n4f, f4 = i - row * n4f;
        float4 v = reinterpret_cast<const float4*>(
                       x + (size_t)(rowBase + row) * nfeat)[f4];
        float* d = xs + row * XPAD + (f4 << 2);
        d[0] = v.x; d[1] = v.y; d[2] = v.z; d[3] = v.w;
    }
    if (threadIdx.x < ROWS) ys[threadIdx.x] = 0.f;
    __syncthreads();

    const int chunk = threadIdx.x >> 5;      // warp == chunk
    const int lane  = threadIdx.x & 31;

    const float* xr0 = xs + lane * XPAD;     // lane owns rows lane and lane+32
    const float ec = g_empty[chunk];
    float y0 = ec, y1 = ec;
    float p0 = 1.f, p1 = 1.f;

    const float4* __restrict__ mp = g_meta + g_chunk_start[chunk];
    const int n = g_chunk_start[chunk + 1] - g_chunk_start[chunk];  // mult of 8

    // e clamped away from 0 so p==inf never meets e==0 (no NaN); p may reach
    // inf, then rcp gives 0 which matches reference underflow-to-zero.
#define EVAL(mm, f, off) fmaxf(ex2a(fmaf((mm).x, xr0[(f) + (off)], (mm).y)), 1e-37f)

    // Flush only possible at atom3 of a group: no per-atom flags/SELs.
#define PROCESS(m0, m1, m2, m3)                                        \
    {                                                                  \
        int f0 = __float_as_int((m0).z);                               \
        int f1 = __float_as_int((m1).z);                               \
        int f2 = __float_as_int((m2).z);                               \
        int fz3 = __float_as_int((m3).z);                              \
        int f3 = fz3 & 0x7fffffff;                                     \
        float e00 = EVAL(m0, f0, 0),         e01 = EVAL(m1, f1, 0);    \
        float e02 = EVAL(m2, f2, 0),         e03 = EVAL(m3, f3, 0);    \
        float e10 = EVAL(m0, f0, 32 * XPAD), e11 = EVAL(m1, f1, 32 * XPAD); \
        float e12 = EVAL(m2, f2, 32 * XPAD), e13 = EVAL(m3, f3, 32 * XPAD); \
        p0 = fmaf(p0, e00, p0); p0 = fmaf(p0, e01, p0);                \
        p0 = fmaf(p0, e02, p0); p0 = fmaf(p0, e03, p0);                \
        p1 = fmaf(p1, e10, p1); p1 = fmaf(p1, e11, p1);                \
        p1 = fmaf(p1, e12, p1); p1 = fmaf(p1, e13, p1);                \
        if (fz3 < 0) {                                                 \
            y0 = fmaf((m3).w, rcpa(p0), y0);                           \
            y1 = fmaf((m3).w, rcpa(p1), y1);                           \
            p0 = 1.f; p1 = 1.f;                                        \
        }                                                              \
    }

    if (n > 0) {
        // 2-group double-buffered software pipeline; no register copies.
        float4 a0 = mp[0], a1 = mp[1], a2 = mp[2], a3 = mp[3];
        for (int i = 0; i < n; i += 8) {
            float4 b0 = mp[i + 4], b1 = mp[i + 5];
            float4 b2 = mp[i + 6], b3 = mp[i + 7];
            PROCESS(a0, a1, a2, a3);
            a0 = mp[i + 8]; a1 = mp[i + 9];      // overreads land in the
            a2 = mp[i + 10]; a3 = mp[i + 11];    // oversized g_meta (unused)
            PROCESS(b0, b1, b2, b3);
        }
    }

    atomicAdd(&ys[lane], y0);
    atomicAdd(&ys[lane + 32], y1);
    __syncthreads();
    if (threadIdx.x < ROWS)
        y[rowBase + threadIdx.x] = ys[threadIdx.x];
}

extern "C" void kernel_launch(void* const* d_in, const int* in_sizes, int n_in,
                              void* d_out, int out_size) {
    const float* x    = (const float*)d_in[0];
    const float* w    = (const float*)d_in[1];
    const float* eta  = (const float*)d_in[2];
    const float* leaf = (const float*)d_in[3];
    const float* gate = (const float*)d_in[4];
    const int*   fid  = (const int*)d_in[5];
    const int*   csgn = (const int*)d_in[6];
    const int*   cids = (const int*)d_in[7];

    const int n_atoms   = in_sizes[1];
    const int n_clauses = in_sizes[3];
    const int batch     = out_size;
    const int nfeat     = in_sizes[0] / batch;
    const int cpc       = n_clauses / NCHUNKS;

    void* empty_ptr = nullptr;
    cudaGetSymbolAddress(&empty_ptr, g_empty);
    cudaMemsetAsync(empty_ptr, 0, NCHUNKS * sizeof(float));

    size_t setup_smem = (size_t)n_atoms * 4 + (size_t)n_clauses * 16;
    cudaFuncSetAttribute(cln_setup, cudaFuncAttributeMaxDynamicSharedMemorySize,
                         (int)setup_smem);
    cln_setup<<<1, THREADS, setup_smem>>>(w, eta, leaf, gate, fid, csgn, cids,
                                          n_atoms, n_clauses, cpc);

    size_t smem = (size_t)ROWS * XPAD * sizeof(float);
    cudaFuncSetAttribute(cln_main, cudaFuncAttributeMaxDynamicSharedMemorySize,
                         (int)smem);
    cln_main<<<batch / ROWS, THREADS, smem>>>(x, (float*)d_out, nfeat);
}

// round 12
// speedup vs baseline: 1.0332x; 1.0332x over previous
#include <cuda_runtime.h>

#define NCHUNKS 32
#define ROWS    64
#define THREADS 1024
#define XPAD    257               // smem row stride in floats (conflict-free)
#define MAX_ATOMS   16384
#define MAX_CLAUSES 4096

// Padded per-atom metadata stream. Every clause is padded to a multiple of 4
// atoms, every chunk to a multiple of 8. Flush can only occur on atom3 of a
// 4-atom group (bit31 of .z set there; .w = gate*leaf of the clause).
// Identity pad atoms: {0,-1000,0,0} -> e underflows -> clamp -> p unchanged.
// arg = A'*x[fid] + B' ; e = exp2(arg) ; clause = 1/prod(1+e)
__device__ float4 g_meta[MAX_ATOMS];
__device__ int    g_chunk_start[NCHUNKS + 1]; // 8-aligned padded ranges
__device__ float  g_empty[NCHUNKS];           // sum g over EMPTY clauses per chunk

__device__ __forceinline__ float ex2a(float a) {
    float r; asm("ex2.approx.f32 %0, %1;" : "=f"(r) : "f"(a)); return r;
}
__device__ __forceinline__ float rcpa(float a) {
    float r; asm("rcp.approx.f32 %0, %1;" : "=f"(r) : "f"(a)); return r;
}

// Lean single-block setup: no binary searches (boundary detection), no
// block-wide scan barriers (one-warp shfl scan), no separate memset.
__global__ __launch_bounds__(THREADS)
void cln_setup(const float* __restrict__ w,
               const float* __restrict__ eta,
               const float* __restrict__ leaf,
               const float* __restrict__ gate,
               const int* __restrict__ fid,
               const int* __restrict__ csgn,
               const int* __restrict__ cids,
               int n_atoms, int n_clauses, int cpc) {
    extern __shared__ int sm[];
    int*   s_cids = sm;                      // n_atoms
    int*   s_src  = sm + n_atoms;            // n_clauses
    int*   s_last = s_src + n_clauses;       // n_clauses
    int*   s_plen = s_last + n_clauses;      // n_clauses
    int*   s_dst  = s_plen + n_clauses;      // n_clauses (abs padded offset)
    float* s_g    = (float*)(s_dst + n_clauses);

    const int tid = threadIdx.x;
    const float L2E = 1.4426950408889634f;

    for (int i = tid; i < n_atoms; i += THREADS) s_cids[i] = cids[i];
    if (tid < n_clauses) s_src[tid] = -1;
    if (tid < NCHUNKS)   g_empty[tid] = 0.f;
    __syncthreads();

    // clause boundaries by streaming detection (no searches)
    for (int i = tid; i < n_atoms; i += THREADS) {
        int c = s_cids[i];
        if (i == 0 || s_cids[i - 1] != c) s_src[c]  = i;
        if (i == n_atoms - 1 || s_cids[i + 1] != c) s_last[c] = i;
    }
    __syncthreads();

    // clause-parallel: lengths, g, empty sums
    if (tid < n_clauses) {
        float g = gate[tid] * leaf[tid];
        s_g[tid] = g;
        int src = s_src[tid];
        int len = (src < 0) ? 0 : (s_last[tid] - src + 1);
        s_plen[tid] = (len + 3) & ~3;
        if (len == 0) atomicAdd(&g_empty[tid / cpc], g);
    }
    __syncthreads();

    // one-warp scan: lane k owns chunk k (cpc clauses, serial), shfl combine
    if (tid < 32) {
        int rel = 0;
        for (int j = 0; j < cpc; ++j) {
            int c = tid * cpc + j;
            s_dst[c] = rel;                  // chunk-relative for now
            rel += s_plen[c];
        }
        int clen = rel;                      // unpadded chunk len (mult of 4)
        int ctp  = (rel + 7) & ~7;           // padded chunk len (mult of 8)
        // exclusive scan of ctp across 32 lanes
        int base = ctp;
        #pragma unroll
        for (int d = 1; d < 32; d <<= 1) {
            int v = __shfl_up_sync(0xffffffff, base, d);
            if (tid >= d) base += v;
        }
        int total = __shfl_sync(0xffffffff, base, 31);
        base -= ctp;                         // exclusive
        g_chunk_start[tid] = base;
        if (tid == 31) g_chunk_start[NCHUNKS] = total;
        s_src[n_clauses > tid ? 0 : 0] = s_src[0]; // no-op keep
        // record base for clause-dst fixup
        s_plen[n_clauses + 0 == 0 ? 0 : 0] = s_plen[0]; // no-op keep
        // stash base in s_dst fixup pass below via shared chunk base array
        ((int*)s_g)[n_clauses + tid] = 0;    // unused slot guard (s_g sized below)
        // chunk pads (identity, NON-flush): slots [clen, ctp)
        for (int a = clen; a < ctp; ++a)
            g_meta[base + a] = make_float4(0.f, -1000.f, 0.f, 0.f);
        // write base where the fixup pass can read it
        s_last[tid] = base;                  // s_last reusable now (chunk base)
    }
    __syncthreads();
    if (tid < n_clauses) s_dst[tid] += s_last[tid / cpc];
    __syncthreads();

    // atom-parallel meta build (coalesced input loads, computed scatter)
    for (int i = tid; i < n_atoms; i += THREADS) {
        int c = s_cids[i];
        int j = i - s_src[c];
        float sB = (csgn[i] == 0) ? -100.0f : 100.0f;   // sign * B_CONST
        float A2 = -sB * w[i] * L2E;
        float B2 = -sB * (0.01f - eta[i]) * L2E;        // EPS = 0.01
        int fz = fid[i];
        float gg = 0.f;
        if (j == s_plen[c] - 1) { fz |= 0x80000000; gg = s_g[c]; }
        g_meta[s_dst[c] + j] = make_float4(A2, B2, __int_as_float(fz), gg);
    }
    // clause pads (identity; flush flag + g on final padded slot)
    if (tid < n_clauses && s_src[tid] >= 0) {
        int plen = s_plen[tid];
        int len  = plen - 3;                 // lower bound; recompute exactly:
        len = (s_dst[tid], plen);            // (placeholder removed below)
        // exact len: last - src + 1
        // (s_last now holds chunk bases; recover len from plen & stored srcs)
        // We recompute from original data: re-derive last atom index
        // Simpler: pads are slots [real_len, plen); real_len = ?
        // real_len was (plen was (len+3)&~3) -> len in (plen-3..plen]
        // Use cids to find: atom s_src[tid]+k belongs to clause while k<len.
        int src = s_src[tid];
        int l = plen - 3;
        while (src + l < n_atoms && l < plen && s_cids[src + l] == tid) ++l;
        int dst = s_dst[tid];
        for (int j = l; j < plen; ++j) {
            int fz = 0; float gg = 0.f;
            if (j == plen - 1) { fz = 0x80000000; gg = s_g[tid]; }
            g_meta[dst + j] = make_float4(0.f, -1000.f, __int_as_float(fz), gg);
        }
    }
}

__global__ __launch_bounds__(THREADS, 1)
void cln_main(const float* __restrict__ x, float* __restrict__ y, int nfeat) {
    extern __shared__ float xs[];            // ROWS * XPAD floats
    __shared__ float ys[ROWS];

    const int rowBase = blockIdx.x * ROWS;

    // Stage 64 rows of x into shared (coalesced float4 loads)
    const int n4f = nfeat >> 2;
    for (int i = threadIdx.x; i < ROWS * n4f; i += THREADS) {
        int row = i / n4f, f4 = i - row * n4f;
        float4 v = reinterpret_cast<const float4*>(
                       x + (size_t)(rowBase + row) * nfeat)[f4];
        float* d = xs + row * XPAD + (f4 << 2);
        d[0] = v.x; d[1] = v.y; d[2] = v.z; d[3] = v.w;
    }
    if (threadIdx.x < ROWS) ys[threadIdx.x] = 0.f;
    __syncthreads();

    const int chunk = threadIdx.x >> 5;      // warp == chunk
    const int lane  = threadIdx.x & 31;

    const float* xr0 = xs + lane * XPAD;     // lane owns rows lane and lane+32
    const float ec = g_empty[chunk];
    float y0 = ec, y1 = ec;
    float p0 = 1.f, p1 = 1.f;

    const float4* __restrict__ mp = g_meta + g_chunk_start[chunk];
    const int n = g_chunk_start[chunk + 1] - g_chunk_start[chunk];  // mult of 8

    // e clamped away from 0 so p==inf never meets e==0 (no NaN); p may reach
    // inf, then rcp gives 0 which matches reference underflow-to-zero.
#define EVAL(mm, f, off) fmaxf(ex2a(fmaf((mm).x, xr0[(f) + (off)], (mm).y)), 1e-37f)

    // Flush only possible at atom3 of a group: no per-atom flags/SELs.
#define PROCESS(m0, m1, m2, m3)                                        \
    {                                                                  \
        int f0 = __float_as_int((m0).z);                               \
        int f1 = __float_as_int((m1).z);                               \
        int f2 = __float_as_int((m2).z);                               \
        int fz3 = __float_as_int((m3).z);                              \
        int f3 = fz3 & 0x7fffffff;                                     \
        float e00 = EVAL(m0, f0, 0),         e01 = EVAL(m1, f1, 0);    \
        float e02 = EVAL(m2, f2, 0),         e03 = EVAL(m3, f3, 0);    \
        float e10 = EVAL(m0, f0, 32 * XPAD), e11 = EVAL(m1, f1, 32 * XPAD); \
        float e12 = EVAL(m2, f2, 32 * XPAD), e13 = EVAL(m3, f3, 32 * XPAD); \
        p0 = fmaf(p0, e00, p0); p0 = fmaf(p0, e01, p0);                \
        p0 = fmaf(p0, e02, p0); p0 = fmaf(p0, e03, p0);                \
        p1 = fmaf(p1, e10, p1); p1 = fmaf(p1, e11, p1);                \
        p1 = fmaf(p1, e12, p1); p1 = fmaf(p1, e13, p1);                \
        if (fz3 < 0) {                                                 \
            y0 = fmaf((m3).w, rcpa(p0), y0);                           \
            y1 = fmaf((m3).w, rcpa(p1), y1);                           \
            p0 = 1.f; p1 = 1.f;                                        \
        }                                                              \
    }

    if (n > 0) {
        // 2-group double-buffered software pipeline; no register copies.
        float4 a0 = mp[0], a1 = mp[1], a2 = mp[2], a3 = mp[3];
        for (int i = 0; i < n; i += 8) {
            float4 b0 = mp[i + 4], b1 = mp[i + 5];
            float4 b2 = mp[i + 6], b3 = mp[i + 7];
            PROCESS(a0, a1, a2, a3);
            a0 = mp[i + 8];  a1 = mp[i + 9];     // overreads land in the
            a2 = mp[i + 10]; a3 = mp[i + 11];    // oversized g_meta (unused)
            PROCESS(b0, b1, b2, b3);
        }
    }

    atomicAdd(&ys[lane], y0);
    atomicAdd(&ys[lane + 32], y1);
    __syncthreads();
    if (threadIdx.x < ROWS)
        y[rowBase + threadIdx.x] = ys[threadIdx.x];
}

extern "C" void kernel_launch(void* const* d_in, const int* in_sizes, int n_in,
                              void* d_out, int out_size) {
    const float* x    = (const float*)d_in[0];
    const float* w    = (const float*)d_in[1];
    const float* eta  = (const float*)d_in[2];
    const float* leaf = (const float*)d_in[3];
    const float* gate = (const float*)d_in[4];
    const int*   fid  = (const int*)d_in[5];
    const int*   csgn = (const int*)d_in[6];
    const int*   cids = (const int*)d_in[7];

    const int n_atoms   = in_sizes[1];
    const int n_clauses = in_sizes[3];
    const int batch     = out_size;
    const int nfeat     = in_sizes[0] / batch;
    const int cpc       = n_clauses / NCHUNKS;

    // smem: cids + 5 clause tables (+64 slack for the scan scratch)
    size_t setup_smem = (size_t)n_atoms * 4 + (size_t)(n_clauses + 64) * 20;
    cudaFuncSetAttribute(cln_setup, cudaFuncAttributeMaxDynamicSharedMemorySize,
                         (int)setup_smem);
    cln_setup<<<1, THREADS, setup_smem>>>(w, eta, leaf, gate, fid, csgn, cids,
                                          n_atoms, n_clauses, cpc);

    size_t smem = (size_t)ROWS * XPAD * sizeof(float);
    cudaFuncSetAttribute(cln_main, cudaFuncAttributeMaxDynamicSharedMemorySize,
                         (int)smem);
    cln_main<<<batch / ROWS, THREADS, smem>>>(x, (float*)d_out, nfeat);
}